// round 2
// baseline (speedup 1.0000x reference)
#include <cuda_runtime.h>

#define N_NODES 50000
#define N_EDGES 600000
#define D 128
#define D2 256
#define NLAYERS 5

// ---------------- scratch (static device memory; no allocations) -------------
__device__ float g_h[N_NODES * D];      // current node features
__device__ float g_z[N_NODES * D];      // z0 (pre-GEMM1), later y2 (post-GEMM2)
__device__ float g_y1[N_NODES * D2];    // GEMM1 output
__device__ float g_stats1[2 * D2];      // col sum / sumsq for BN1
__device__ float g_stats2[2 * D];       // col sum / sumsq for BN2
__device__ float g_scale1[D2], g_shift1[D2];
__device__ float g_scale2[D], g_shift2[D];

// ---------------- node embedding: h = sum_f atom_emb[f][x[:,f]] --------------
__global__ void embed_kernel(const int* __restrict__ x,
                             const float* __restrict__ atom_emb) {
    int idx = blockIdx.x * blockDim.x + threadIdx.x;
    int node = idx >> 5, lane = idx & 31;     // 32 lanes * float4 = 128 floats
    if (node >= N_NODES) return;
    const int* xr = x + node * 9;
    float4 acc = make_float4(0.f, 0.f, 0.f, 0.f);
#pragma unroll
    for (int f = 0; f < 9; f++) {
        int v = __ldg(xr + f);
        float4 t = ((const float4*)(atom_emb + (size_t)(f * 64 + v) * D))[lane];
        acc.x += t.x; acc.y += t.y; acc.z += t.z; acc.w += t.w;
    }
    ((float4*)(g_h + (size_t)node * D))[lane] = acc;
}

// ---------------- z = (1+eps)*h ; zero BN stat accumulators ------------------
__global__ void init_z_kernel(const float* __restrict__ eps_p, int l) {
    int idx = blockIdx.x * blockDim.x + threadIdx.x;
    // FIX (round 1): zero stats with GLOBAL index coverage. Previously only
    // threadIdx.x < 256 of the 512-float g_stats1 got zeroed -> sumsq
    // accumulated across layers/replays -> rel_err 0.647.
    if (idx < 2 * D2) g_stats1[idx] = 0.f;
    if (idx < 2 * D)  g_stats2[idx] = 0.f;
    if (idx >= N_NODES * (D / 4)) return;
    float s = 1.f + __ldg(eps_p + l);
    float4 v = ((const float4*)g_h)[idx];
    v.x *= s; v.y *= s; v.z *= s; v.w *= s;
    ((float4*)g_z)[idx] = v;
}

// ---------------- edge scatter: z[dst] += relu(h[src]+ea)*ew -----------------
__global__ void edge_kernel(const int* __restrict__ edge_index,
                            const int* __restrict__ edge_attr,
                            const float* __restrict__ edge_weight,
                            const float* __restrict__ bond_emb, int l) {
    __shared__ __align__(16) float sb[3 * 8 * D];   // bond table for layer l (12 KB)
    const float* be = bond_emb + (size_t)l * 3 * 8 * D;
    for (int i = threadIdx.x; i < 3 * 8 * D; i += blockDim.x) sb[i] = be[i];
    __syncthreads();

    const int* src = edge_index;
    const int* dst = edge_index + N_EDGES;
    int gw = (blockIdx.x * blockDim.x + threadIdx.x) >> 5;
    int lane = threadIdx.x & 31;
    int nw = (gridDim.x * blockDim.x) >> 5;

    for (int e = gw; e < N_EDGES; e += nw) {
        int s = __ldg(src + e);
        int d = __ldg(dst + e);
        float w = __ldg(edge_weight + e);
        int a0 = __ldg(edge_attr + e * 3 + 0);
        int a1 = __ldg(edge_attr + e * 3 + 1);
        int a2 = __ldg(edge_attr + e * 3 + 2);
        float4 hv = ((const float4*)(g_h + (size_t)s * D))[lane];
        float4 e0 = ((const float4*)(sb + a0 * D))[lane];
        float4 e1 = ((const float4*)(sb + (8 + a1) * D))[lane];
        float4 e2 = ((const float4*)(sb + (16 + a2) * D))[lane];
        float4 m;
        m.x = fmaxf(hv.x + e0.x + e1.x + e2.x, 0.f) * w;
        m.y = fmaxf(hv.y + e0.y + e1.y + e2.y, 0.f) * w;
        m.z = fmaxf(hv.z + e0.z + e1.z + e2.z, 0.f) * w;
        m.w = fmaxf(hv.w + e0.w + e1.w + e2.w, 0.f) * w;
        atomicAdd(((float4*)(g_z + (size_t)d * D)) + lane, m);
    }
}

// ---------------- tiled fp32 GEMM with optional fused input-BN+relu ----------
// C[M x NOUT] = act(A)[M x K] @ W[K x NOUT] + bias, plus column sum/sumsq stats.
// act(a) = INBN ? relu(a*insc[k]+insh[k]) : a   (applied per K-column on load)
template <int K, int NOUT, bool INBN>
__global__ void gemm_kernel(const float* __restrict__ A, const float* __restrict__ W,
                            const float* __restrict__ bias, float* __restrict__ C,
                            const float* __restrict__ insc, const float* __restrict__ insh,
                            float* __restrict__ stats) {
    const int BM = 64, BN = 64, BK = 32;
    __shared__ __align__(16) float As[BK][BM];
    __shared__ __align__(16) float Bs[BK][BN];
    __shared__ float ssum[BN], ssq[BN];

    int tid = threadIdx.x;
    int tx = tid & 15, ty = tid >> 4;
    int rowBase = blockIdx.y * BM;
    int colBase = blockIdx.x * BN;

    float acc[4][4] = {};

    for (int kt = 0; kt < K; kt += BK) {
        // load A tile (64 rows x 32 k), transpose into As[k][row]
#pragma unroll
        for (int it = 0; it < 2; it++) {
            int r = (tid >> 3) + it * 32;
            int kc = (tid & 7) * 4;
            int grow = rowBase + r;
            float4 a = make_float4(0.f, 0.f, 0.f, 0.f);
            if (grow < N_NODES)
                a = *(const float4*)(A + (size_t)grow * K + kt + kc);
            if (INBN) {
                float s0 = insc[kt + kc + 0], h0 = insh[kt + kc + 0];
                float s1 = insc[kt + kc + 1], h1 = insh[kt + kc + 1];
                float s2 = insc[kt + kc + 2], h2 = insh[kt + kc + 2];
                float s3 = insc[kt + kc + 3], h3 = insh[kt + kc + 3];
                a.x = fmaxf(fmaf(a.x, s0, h0), 0.f);
                a.y = fmaxf(fmaf(a.y, s1, h1), 0.f);
                a.z = fmaxf(fmaf(a.z, s2, h2), 0.f);
                a.w = fmaxf(fmaf(a.w, s3, h3), 0.f);
            }
            As[kc + 0][r] = a.x; As[kc + 1][r] = a.y;
            As[kc + 2][r] = a.z; As[kc + 3][r] = a.w;
        }
        // load B tile (32 k x 64 cols)
#pragma unroll
        for (int it = 0; it < 2; it++) {
            int kr = (tid >> 4) + it * 16;
            int cc = (tid & 15) * 4;
            float4 b = *(const float4*)(W + (size_t)(kt + kr) * NOUT + colBase + cc);
            *(float4*)&Bs[kr][cc] = b;
        }
        __syncthreads();
#pragma unroll
        for (int k = 0; k < BK; k++) {
            float4 av = *(const float4*)&As[k][ty * 4];
            float4 bv = *(const float4*)&Bs[k][tx * 4];
            float aa[4] = {av.x, av.y, av.z, av.w};
            float bb[4] = {bv.x, bv.y, bv.z, bv.w};
#pragma unroll
            for (int i = 0; i < 4; i++)
#pragma unroll
                for (int j = 0; j < 4; j++)
                    acc[i][j] = fmaf(aa[i], bb[j], acc[i][j]);
        }
        __syncthreads();
    }

    // epilogue: bias add, store, per-column stats
    float bcol[4];
#pragma unroll
    for (int j = 0; j < 4; j++) bcol[j] = bias[colBase + tx * 4 + j];

    float psum[4] = {}, psq[4] = {};
#pragma unroll
    for (int i = 0; i < 4; i++) {
        int r = rowBase + ty * 4 + i;
        if (r < N_NODES) {
            float v0 = acc[i][0] + bcol[0];
            float v1 = acc[i][1] + bcol[1];
            float v2 = acc[i][2] + bcol[2];
            float v3 = acc[i][3] + bcol[3];
            *(float4*)(C + (size_t)r * NOUT + colBase + tx * 4) = make_float4(v0, v1, v2, v3);
            psum[0] += v0; psq[0] += v0 * v0;
            psum[1] += v1; psq[1] += v1 * v1;
            psum[2] += v2; psq[2] += v2 * v2;
            psum[3] += v3; psq[3] += v3 * v3;
        }
    }
    if (tid < BN) { ssum[tid] = 0.f; ssq[tid] = 0.f; }
    __syncthreads();
#pragma unroll
    for (int j = 0; j < 4; j++) {
        atomicAdd(&ssum[tx * 4 + j], psum[j]);
        atomicAdd(&ssq[tx * 4 + j], psq[j]);
    }
    __syncthreads();
    if (tid < BN) {
        atomicAdd(&stats[colBase + tid], ssum[tid]);
        atomicAdd(&stats[NOUT + colBase + tid], ssq[tid]);
    }
}

// ---------------- BN stats -> scale/shift ------------------------------------
__global__ void finalize_kernel(const float* __restrict__ stats,
                                const float* __restrict__ g, const float* __restrict__ b,
                                float* __restrict__ scale, float* __restrict__ shift, int C) {
    int c = threadIdx.x;
    if (c < C) {
        const float invn = 1.f / (float)N_NODES;
        float m = stats[c] * invn;
        float var = stats[C + c] * invn - m * m;
        float sc = g[c] * rsqrtf(var + 1e-5f);
        scale[c] = sc;
        shift[c] = b[c] - m * sc;
    }
}

// ---------------- apply BN2 (+ optional relu); write h or final output -------
__global__ void bn_apply_kernel(float* __restrict__ final_out, int relu, int to_out) {
    int idx = blockIdx.x * blockDim.x + threadIdx.x;
    if (idx >= N_NODES * (D / 4)) return;
    int c4 = idx & 31;
    float4 v = ((const float4*)g_z)[idx];
    float4 sc = ((const float4*)g_scale2)[c4];
    float4 sh = ((const float4*)g_shift2)[c4];
    v.x = fmaf(v.x, sc.x, sh.x);
    v.y = fmaf(v.y, sc.y, sh.y);
    v.z = fmaf(v.z, sc.z, sh.z);
    v.w = fmaf(v.w, sc.w, sh.w);
    if (relu) {
        v.x = fmaxf(v.x, 0.f); v.y = fmaxf(v.y, 0.f);
        v.z = fmaxf(v.z, 0.f); v.w = fmaxf(v.w, 0.f);
    }
    float4* dst = to_out ? (float4*)final_out : (float4*)g_h;
    dst[idx] = v;
}

// ---------------- launcher ---------------------------------------------------
extern "C" void kernel_launch(void* const* d_in, const int* in_sizes, int n_in,
                              void* d_out, int out_size) {
    const int*   x           = (const int*)d_in[0];
    const int*   edge_index  = (const int*)d_in[1];
    const int*   edge_attr   = (const int*)d_in[2];
    const float* edge_weight = (const float*)d_in[3];
    const float* atom_emb    = (const float*)d_in[4];
    const float* bond_emb    = (const float*)d_in[5];
    const float* W1          = (const float*)d_in[6];
    const float* b1          = (const float*)d_in[7];
    const float* bn1_g       = (const float*)d_in[8];
    const float* bn1_b       = (const float*)d_in[9];
    const float* W2          = (const float*)d_in[10];
    const float* b2          = (const float*)d_in[11];
    const float* eps_p       = (const float*)d_in[12];
    const float* bn_g        = (const float*)d_in[13];
    const float* bn_b        = (const float*)d_in[14];
    float* out = (float*)d_out;

    // device addresses of scratch symbols (pure lookup, capture-safe)
    float *p_z, *p_y1, *p_sc1, *p_sh1, *p_st1, *p_st2, *p_sc2, *p_sh2;
    cudaGetSymbolAddress((void**)&p_z,   g_z);
    cudaGetSymbolAddress((void**)&p_y1,  g_y1);
    cudaGetSymbolAddress((void**)&p_sc1, g_scale1);
    cudaGetSymbolAddress((void**)&p_sh1, g_shift1);
    cudaGetSymbolAddress((void**)&p_st1, g_stats1);
    cudaGetSymbolAddress((void**)&p_st2, g_stats2);
    cudaGetSymbolAddress((void**)&p_sc2, g_scale2);
    cudaGetSymbolAddress((void**)&p_sh2, g_shift2);

    const int ELT_BLOCKS = (N_NODES * (D / 4) + 255) / 256;

    embed_kernel<<<(N_NODES * 32 + 255) / 256, 256>>>(x, atom_emb);

    for (int l = 0; l < NLAYERS; l++) {
        init_z_kernel<<<ELT_BLOCKS, 256>>>(eps_p, l);
        edge_kernel<<<1184, 256>>>(edge_index, edge_attr, edge_weight, bond_emb, l);

        // GEMM1: y1 = z @ W1[l] + b1[l], collect BN1 stats
        gemm_kernel<D, D2, false><<<dim3(D2 / 64, (N_NODES + 63) / 64), 256>>>(
            p_z, W1 + (size_t)l * D * D2, b1 + (size_t)l * D2, p_y1,
            nullptr, nullptr, p_st1);
        finalize_kernel<<<1, 256>>>(p_st1, bn1_g + (size_t)l * D2, bn1_b + (size_t)l * D2,
                                    p_sc1, p_sh1, D2);

        // GEMM2: y2 = relu(bn1(y1)) @ W2[l] + b2[l], collect BN2 stats
        gemm_kernel<D2, D, true><<<dim3(D / 64, (N_NODES + 63) / 64), 256>>>(
            p_y1, W2 + (size_t)l * D2 * D, b2 + (size_t)l * D, p_z,
            p_sc1, p_sh1, p_st2);
        finalize_kernel<<<1, 128>>>(p_st2, bn_g + (size_t)l * D, bn_b + (size_t)l * D,
                                    p_sc2, p_sh2, D);

        int last = (l == NLAYERS - 1);
        bn_apply_kernel<<<ELT_BLOCKS, 256>>>(out, /*relu=*/!last, /*to_out=*/last);
    }
    (void)in_sizes; (void)n_in; (void)out_size;
}